// round 9
// baseline (speedup 1.0000x reference)
#include <cuda_runtime.h>

// Single-layer ReLU RNN (batch_first), h0 = 0, then out = tanh(W_out h_T + b_out).
// One thread per batch row. Hidden dim 5 padded to 6 and computed as 3 packed
// f32x2 accumulators via Blackwell fma.rn.f32x2 (halves FMA-pipe instruction
// count vs scalar FFMA). Input row streamed via double-buffered LDG.128.

typedef unsigned long long u64;

#define NIN_  3
#define NHID_ 5

__device__ __forceinline__ u64 pk2(float lo, float hi) {
    u64 r; asm("mov.b64 %0, {%1, %2};" : "=l"(r) : "f"(lo), "f"(hi)); return r;
}
__device__ __forceinline__ u64 dup2(float v) {
    u64 r; asm("mov.b64 %0, {%1, %1};" : "=l"(r) : "f"(v)); return r;
}
__device__ __forceinline__ u64 fma2_(u64 a, u64 b, u64 c) {
    u64 d; asm("fma.rn.f32x2 %0, %1, %2, %3;" : "=l"(d) : "l"(a), "l"(b), "l"(c)); return d;
}
__device__ __forceinline__ float lo2(u64 v) { return __uint_as_float((unsigned)v); }
__device__ __forceinline__ float hi2(u64 v) { return __uint_as_float((unsigned)(v >> 32)); }

struct WPack {
    u64 wi[NIN_][3];   // input weights: [input i][hidden pair p] = (W_ih[2p][i], W_ih[2p+1][i])
    u64 wh[NHID_][3];  // recurrent:     [hidden k][pair p]       = (W_hh[2p][k], W_hh[2p+1][k])
    u64 bias[3];       // b_ih + b_hh, packed over hidden pairs (pad = 0)
};

__device__ __forceinline__ void rnn_step(float x0, float x1, float x2,
                                         const WPack& W, u64 hd[NHID_]) {
    u64 a0 = W.bias[0], a1 = W.bias[1], a2 = W.bias[2];
    u64 d;
    d = dup2(x0);
    a0 = fma2_(d, W.wi[0][0], a0); a1 = fma2_(d, W.wi[0][1], a1); a2 = fma2_(d, W.wi[0][2], a2);
    d = dup2(x1);
    a0 = fma2_(d, W.wi[1][0], a0); a1 = fma2_(d, W.wi[1][1], a1); a2 = fma2_(d, W.wi[1][2], a2);
    d = dup2(x2);
    a0 = fma2_(d, W.wi[2][0], a0); a1 = fma2_(d, W.wi[2][1], a1); a2 = fma2_(d, W.wi[2][2], a2);
#pragma unroll
    for (int k = 0; k < NHID_; ++k) {
        a0 = fma2_(hd[k], W.wh[k][0], a0);
        a1 = fma2_(hd[k], W.wh[k][1], a1);
        a2 = fma2_(hd[k], W.wh[k][2], a2);
    }
    // relu + re-duplicate each hidden scalar into both halves for next step
    hd[0] = dup2(fmaxf(lo2(a0), 0.f));
    hd[1] = dup2(fmaxf(hi2(a0), 0.f));
    hd[2] = dup2(fmaxf(lo2(a1), 0.f));
    hd[3] = dup2(fmaxf(hi2(a1), 0.f));
    hd[4] = dup2(fmaxf(lo2(a2), 0.f));
    // hi half of a2 is the padded (zero-weight) hidden unit; never read.
}

// 16 timesteps = 48 floats = 12 float4 from the register buffer.
__device__ __forceinline__ void steps16(const float4 (&bf)[12], const WPack& W, u64 hd[NHID_]) {
#pragma unroll
    for (int g = 0; g < 4; ++g) {
        float4 p = bf[3*g + 0];
        float4 q = bf[3*g + 1];
        float4 r = bf[3*g + 2];
        rnn_step(p.x, p.y, p.z, W, hd);
        rnn_step(p.w, q.x, q.y, W, hd);
        rnn_step(q.z, q.w, r.x, W, hd);
        rnn_step(r.y, r.z, r.w, W, hd);
    }
}

__global__ void __launch_bounds__(32, 1) rnn_scan_kernel(
    const float* __restrict__ state,
    const float* __restrict__ W_ih, const float* __restrict__ W_hh,
    const float* __restrict__ b_ih, const float* __restrict__ b_hh,
    const float* __restrict__ W_out, const float* __restrict__ b_out,
    float* __restrict__ out, int B, int T)
{
    int b = blockIdx.x * 32 + threadIdx.x;
    if (b >= B) return;

    // ---- Build packed weights in registers (uniform across threads; L1/L2 broadcast) ----
    WPack W;
#pragma unroll
    for (int p = 0; p < 3; ++p) {
        const int j0 = 2*p, j1 = 2*p + 1;
        const float bl = (j0 < NHID_) ? (b_ih[j0] + b_hh[j0]) : 0.f;
        const float bh = (j1 < NHID_) ? (b_ih[j1] + b_hh[j1]) : 0.f;
        W.bias[p] = pk2(bl, bh);
#pragma unroll
        for (int i = 0; i < NIN_; ++i) {
            const float wl = (j0 < NHID_) ? W_ih[j0*NIN_ + i] : 0.f;
            const float wh = (j1 < NHID_) ? W_ih[j1*NIN_ + i] : 0.f;
            W.wi[i][p] = pk2(wl, wh);
        }
#pragma unroll
        for (int k = 0; k < NHID_; ++k) {
            const float wl = (j0 < NHID_) ? W_hh[j0*NHID_ + k] : 0.f;
            const float wh = (j1 < NHID_) ? W_hh[j1*NHID_ + k] : 0.f;
            W.wh[k][p] = pk2(wl, wh);
        }
    }

    u64 hd[NHID_];
#pragma unroll
    for (int k = 0; k < NHID_; ++k) hd[k] = dup2(0.f);

    const float* row = state + (size_t)b * (size_t)T * NIN_;

    if ((T & 3) == 0) {
        // Fast path: row base is 16B-aligned (T % 4 == 0 -> 12*T % 16 == 0).
        const float4* xr = reinterpret_cast<const float4*>(row);
        const int NC = T / 16;           // 16-step chunks, 12 float4 each
        float4 A[12], Bb[12];
        if (NC > 0) {
#pragma unroll
            for (int i = 0; i < 12; ++i) A[i] = xr[i];
        }
        int c = 0;
        while (c < NC) {
            if (c + 1 < NC) {
#pragma unroll
                for (int i = 0; i < 12; ++i) Bb[i] = xr[(size_t)(c + 1) * 12 + i];
            }
            steps16(A, W, hd);
            if (c + 2 < NC) {
#pragma unroll
                for (int i = 0; i < 12; ++i) A[i] = xr[(size_t)(c + 2) * 12 + i];
            }
            if (c + 1 < NC) steps16(Bb, W, hd);
            c += 2;
        }
        // Remainder steps (T % 16), scalar loads.
        for (int t = NC * 16; t < T; ++t)
            rnn_step(row[3*t + 0], row[3*t + 1], row[3*t + 2], W, hd);
    } else {
        // Generic fallback (unused for T=2048): scalar loads each step.
        for (int t = 0; t < T; ++t)
            rnn_step(row[3*t + 0], row[3*t + 1], row[3*t + 2], W, hd);
    }

    // ---- out = tanh(W_out . h_T + b_out), NOUT = 1 ----
    const float h0 = lo2(hd[0]), h1 = lo2(hd[1]), h2 = lo2(hd[2]);
    const float h3 = lo2(hd[3]), h4 = lo2(hd[4]);
    float acc = b_out[0];
    acc = fmaf(h0, W_out[0],
          fmaf(h1, W_out[1],
          fmaf(h2, W_out[2],
          fmaf(h3, W_out[3],
          fmaf(h4, W_out[4], acc)))));
    out[b] = tanhf(acc);
}

extern "C" void kernel_launch(void* const* d_in, const int* in_sizes, int n_in,
                              void* d_out, int out_size) {
    const float* state = (const float*)d_in[0];   // [B, T, 3]
    const float* W_ih  = (const float*)d_in[1];   // [5, 3]
    const float* W_hh  = (const float*)d_in[2];   // [5, 5]
    const float* b_ih  = (const float*)d_in[3];   // [5]
    const float* b_hh  = (const float*)d_in[4];   // [5]
    const float* W_out = (const float*)d_in[5];   // [1, 5]
    const float* b_out = (const float*)d_in[6];   // [1]

    const int B = out_size;                       // NOUT == 1
    const int T = in_sizes[0] / (B * NIN_);

    const int blocks = (B + 31) / 32;             // 1-warp blocks -> spread across SMs
    rnn_scan_kernel<<<blocks, 32>>>(state, W_ih, W_hh, b_ih, b_hh, W_out, b_out,
                                    (float*)d_out, B, T);
}

// round 10
// speedup vs baseline: 1.0096x; 1.0096x over previous
#include <cuda_runtime.h>

// Single-layer ReLU RNN (batch_first), h0 = 0, then out = tanh(W_out h_T + b_out).
// One thread per batch row. Hidden dim 5 padded to 6 and computed as 3 packed
// f32x2 accumulators via Blackwell fma.rn.f32x2 (halves FMA-pipe instruction
// count vs scalar FFMA). Input row streamed via double-buffered LDG.128.

typedef unsigned long long u64;

#define NIN_  3
#define NHID_ 5

__device__ __forceinline__ u64 pk2(float lo, float hi) {
    u64 r; asm("mov.b64 %0, {%1, %2};" : "=l"(r) : "f"(lo), "f"(hi)); return r;
}
__device__ __forceinline__ u64 dup2(float v) {
    u64 r; asm("mov.b64 %0, {%1, %1};" : "=l"(r) : "f"(v)); return r;
}
__device__ __forceinline__ u64 fma2_(u64 a, u64 b, u64 c) {
    u64 d; asm("fma.rn.f32x2 %0, %1, %2, %3;" : "=l"(d) : "l"(a), "l"(b), "l"(c)); return d;
}
__device__ __forceinline__ float lo2(u64 v) { return __uint_as_float((unsigned)v); }
__device__ __forceinline__ float hi2(u64 v) { return __uint_as_float((unsigned)(v >> 32)); }

struct WPack {
    u64 wi[NIN_][3];   // input weights: [input i][hidden pair p] = (W_ih[2p][i], W_ih[2p+1][i])
    u64 wh[NHID_][3];  // recurrent:     [hidden k][pair p]       = (W_hh[2p][k], W_hh[2p+1][k])
    u64 bias[3];       // b_ih + b_hh, packed over hidden pairs (pad = 0)
};

__device__ __forceinline__ void rnn_step(float x0, float x1, float x2,
                                         const WPack& W, u64 hd[NHID_]) {
    u64 a0 = W.bias[0], a1 = W.bias[1], a2 = W.bias[2];
    u64 d;
    d = dup2(x0);
    a0 = fma2_(d, W.wi[0][0], a0); a1 = fma2_(d, W.wi[0][1], a1); a2 = fma2_(d, W.wi[0][2], a2);
    d = dup2(x1);
    a0 = fma2_(d, W.wi[1][0], a0); a1 = fma2_(d, W.wi[1][1], a1); a2 = fma2_(d, W.wi[1][2], a2);
    d = dup2(x2);
    a0 = fma2_(d, W.wi[2][0], a0); a1 = fma2_(d, W.wi[2][1], a1); a2 = fma2_(d, W.wi[2][2], a2);
#pragma unroll
    for (int k = 0; k < NHID_; ++k) {
        a0 = fma2_(hd[k], W.wh[k][0], a0);
        a1 = fma2_(hd[k], W.wh[k][1], a1);
        a2 = fma2_(hd[k], W.wh[k][2], a2);
    }
    // relu + re-duplicate each hidden scalar into both halves for next step
    hd[0] = dup2(fmaxf(lo2(a0), 0.f));
    hd[1] = dup2(fmaxf(hi2(a0), 0.f));
    hd[2] = dup2(fmaxf(lo2(a1), 0.f));
    hd[3] = dup2(fmaxf(hi2(a1), 0.f));
    hd[4] = dup2(fmaxf(lo2(a2), 0.f));
    // hi half of a2 is the padded (zero-weight) hidden unit; never read.
}

// 16 timesteps = 48 floats = 12 float4 from the register buffer.
__device__ __forceinline__ void steps16(const float4 (&bf)[12], const WPack& W, u64 hd[NHID_]) {
#pragma unroll
    for (int g = 0; g < 4; ++g) {
        float4 p = bf[3*g + 0];
        float4 q = bf[3*g + 1];
        float4 r = bf[3*g + 2];
        rnn_step(p.x, p.y, p.z, W, hd);
        rnn_step(p.w, q.x, q.y, W, hd);
        rnn_step(q.z, q.w, r.x, W, hd);
        rnn_step(r.y, r.z, r.w, W, hd);
    }
}

__global__ void __launch_bounds__(32, 1) rnn_scan_kernel(
    const float* __restrict__ state,
    const float* __restrict__ W_ih, const float* __restrict__ W_hh,
    const float* __restrict__ b_ih, const float* __restrict__ b_hh,
    const float* __restrict__ W_out, const float* __restrict__ b_out,
    float* __restrict__ out, int B, int T)
{
    int b = blockIdx.x * 32 + threadIdx.x;
    if (b >= B) return;

    // ---- Build packed weights in registers (uniform across threads; L1/L2 broadcast) ----
    WPack W;
#pragma unroll
    for (int p = 0; p < 3; ++p) {
        const int j0 = 2*p, j1 = 2*p + 1;
        const float bl = (j0 < NHID_) ? (b_ih[j0] + b_hh[j0]) : 0.f;
        const float bh = (j1 < NHID_) ? (b_ih[j1] + b_hh[j1]) : 0.f;
        W.bias[p] = pk2(bl, bh);
#pragma unroll
        for (int i = 0; i < NIN_; ++i) {
            const float wl = (j0 < NHID_) ? W_ih[j0*NIN_ + i] : 0.f;
            const float wh = (j1 < NHID_) ? W_ih[j1*NIN_ + i] : 0.f;
            W.wi[i][p] = pk2(wl, wh);
        }
#pragma unroll
        for (int k = 0; k < NHID_; ++k) {
            const float wl = (j0 < NHID_) ? W_hh[j0*NHID_ + k] : 0.f;
            const float wh = (j1 < NHID_) ? W_hh[j1*NHID_ + k] : 0.f;
            W.wh[k][p] = pk2(wl, wh);
        }
    }

    u64 hd[NHID_];
#pragma unroll
    for (int k = 0; k < NHID_; ++k) hd[k] = dup2(0.f);

    const float* row = state + (size_t)b * (size_t)T * NIN_;

    if ((T & 3) == 0) {
        // Fast path: row base is 16B-aligned (T % 4 == 0 -> 12*T % 16 == 0).
        const float4* xr = reinterpret_cast<const float4*>(row);
        const int NC = T / 16;           // 16-step chunks, 12 float4 each
        float4 A[12], Bb[12];
        if (NC > 0) {
#pragma unroll
            for (int i = 0; i < 12; ++i) A[i] = xr[i];
        }
        int c = 0;
        while (c < NC) {
            if (c + 1 < NC) {
#pragma unroll
                for (int i = 0; i < 12; ++i) Bb[i] = xr[(size_t)(c + 1) * 12 + i];
            }
            steps16(A, W, hd);
            if (c + 2 < NC) {
#pragma unroll
                for (int i = 0; i < 12; ++i) A[i] = xr[(size_t)(c + 2) * 12 + i];
            }
            if (c + 1 < NC) steps16(Bb, W, hd);
            c += 2;
        }
        // Remainder steps (T % 16), scalar loads.
        for (int t = NC * 16; t < T; ++t)
            rnn_step(row[3*t + 0], row[3*t + 1], row[3*t + 2], W, hd);
    } else {
        // Generic fallback (unused for T=2048): scalar loads each step.
        for (int t = 0; t < T; ++t)
            rnn_step(row[3*t + 0], row[3*t + 1], row[3*t + 2], W, hd);
    }

    // ---- out = tanh(W_out . h_T + b_out), NOUT = 1 ----
    const float h0 = lo2(hd[0]), h1 = lo2(hd[1]), h2 = lo2(hd[2]);
    const float h3 = lo2(hd[3]), h4 = lo2(hd[4]);
    float acc = b_out[0];
    acc = fmaf(h0, W_out[0],
          fmaf(h1, W_out[1],
          fmaf(h2, W_out[2],
          fmaf(h3, W_out[3],
          fmaf(h4, W_out[4], acc)))));
    out[b] = tanhf(acc);
}

extern "C" void kernel_launch(void* const* d_in, const int* in_sizes, int n_in,
                              void* d_out, int out_size) {
    const float* state = (const float*)d_in[0];   // [B, T, 3]
    const float* W_ih  = (const float*)d_in[1];   // [5, 3]
    const float* W_hh  = (const float*)d_in[2];   // [5, 5]
    const float* b_ih  = (const float*)d_in[3];   // [5]
    const float* b_hh  = (const float*)d_in[4];   // [5]
    const float* W_out = (const float*)d_in[5];   // [1, 5]
    const float* b_out = (const float*)d_in[6];   // [1]

    const int B = out_size;                       // NOUT == 1
    const int T = in_sizes[0] / (B * NIN_);

    const int blocks = (B + 31) / 32;             // 1-warp blocks -> spread across SMs
    rnn_scan_kernel<<<blocks, 32>>>(state, W_ih, W_hh, b_ih, b_hh, W_out, b_out,
                                    (float*)d_out, B, T);
}

// round 11
// speedup vs baseline: 1.0099x; 1.0003x over previous
#include <cuda_runtime.h>

// Single-layer ReLU RNN (batch_first), h0 = 0, then out = tanh(W_out h_T + b_out).
// One thread per batch row. Hidden dim 5 padded to 6 and computed as 3 packed
// f32x2 accumulators via Blackwell fma.rn.f32x2 (halves FMA-pipe instruction
// count vs scalar FFMA). Input row streamed via double-buffered LDG.128.

typedef unsigned long long u64;

#define NIN_  3
#define NHID_ 5

__device__ __forceinline__ u64 pk2(float lo, float hi) {
    u64 r; asm("mov.b64 %0, {%1, %2};" : "=l"(r) : "f"(lo), "f"(hi)); return r;
}
__device__ __forceinline__ u64 dup2(float v) {
    u64 r; asm("mov.b64 %0, {%1, %1};" : "=l"(r) : "f"(v)); return r;
}
__device__ __forceinline__ u64 fma2_(u64 a, u64 b, u64 c) {
    u64 d; asm("fma.rn.f32x2 %0, %1, %2, %3;" : "=l"(d) : "l"(a), "l"(b), "l"(c)); return d;
}
__device__ __forceinline__ float lo2(u64 v) { return __uint_as_float((unsigned)v); }
__device__ __forceinline__ float hi2(u64 v) { return __uint_as_float((unsigned)(v >> 32)); }

struct WPack {
    u64 wi[NIN_][3];   // input weights: [input i][hidden pair p] = (W_ih[2p][i], W_ih[2p+1][i])
    u64 wh[NHID_][3];  // recurrent:     [hidden k][pair p]       = (W_hh[2p][k], W_hh[2p+1][k])
    u64 bias[3];       // b_ih + b_hh, packed over hidden pairs (pad = 0)
};

__device__ __forceinline__ void rnn_step(float x0, float x1, float x2,
                                         const WPack& W, u64 hd[NHID_]) {
    u64 a0 = W.bias[0], a1 = W.bias[1], a2 = W.bias[2];
    u64 d;
    d = dup2(x0);
    a0 = fma2_(d, W.wi[0][0], a0); a1 = fma2_(d, W.wi[0][1], a1); a2 = fma2_(d, W.wi[0][2], a2);
    d = dup2(x1);
    a0 = fma2_(d, W.wi[1][0], a0); a1 = fma2_(d, W.wi[1][1], a1); a2 = fma2_(d, W.wi[1][2], a2);
    d = dup2(x2);
    a0 = fma2_(d, W.wi[2][0], a0); a1 = fma2_(d, W.wi[2][1], a1); a2 = fma2_(d, W.wi[2][2], a2);
#pragma unroll
    for (int k = 0; k < NHID_; ++k) {
        a0 = fma2_(hd[k], W.wh[k][0], a0);
        a1 = fma2_(hd[k], W.wh[k][1], a1);
        a2 = fma2_(hd[k], W.wh[k][2], a2);
    }
    // relu + re-duplicate each hidden scalar into both halves for next step
    hd[0] = dup2(fmaxf(lo2(a0), 0.f));
    hd[1] = dup2(fmaxf(hi2(a0), 0.f));
    hd[2] = dup2(fmaxf(lo2(a1), 0.f));
    hd[3] = dup2(fmaxf(hi2(a1), 0.f));
    hd[4] = dup2(fmaxf(lo2(a2), 0.f));
    // hi half of a2 is the padded (zero-weight) hidden unit; never read.
}

// 16 timesteps = 48 floats = 12 float4 from the register buffer.
__device__ __forceinline__ void steps16(const float4 (&bf)[12], const WPack& W, u64 hd[NHID_]) {
#pragma unroll
    for (int g = 0; g < 4; ++g) {
        float4 p = bf[3*g + 0];
        float4 q = bf[3*g + 1];
        float4 r = bf[3*g + 2];
        rnn_step(p.x, p.y, p.z, W, hd);
        rnn_step(p.w, q.x, q.y, W, hd);
        rnn_step(q.z, q.w, r.x, W, hd);
        rnn_step(r.y, r.z, r.w, W, hd);
    }
}

__global__ void __launch_bounds__(32, 1) rnn_scan_kernel(
    const float* __restrict__ state,
    const float* __restrict__ W_ih, const float* __restrict__ W_hh,
    const float* __restrict__ b_ih, const float* __restrict__ b_hh,
    const float* __restrict__ W_out, const float* __restrict__ b_out,
    float* __restrict__ out, int B, int T)
{
    int b = blockIdx.x * 32 + threadIdx.x;
    if (b >= B) return;

    // ---- Build packed weights in registers (uniform across threads; L1/L2 broadcast) ----
    WPack W;
#pragma unroll
    for (int p = 0; p < 3; ++p) {
        const int j0 = 2*p, j1 = 2*p + 1;
        const float bl = (j0 < NHID_) ? (b_ih[j0] + b_hh[j0]) : 0.f;
        const float bh = (j1 < NHID_) ? (b_ih[j1] + b_hh[j1]) : 0.f;
        W.bias[p] = pk2(bl, bh);
#pragma unroll
        for (int i = 0; i < NIN_; ++i) {
            const float wl = (j0 < NHID_) ? W_ih[j0*NIN_ + i] : 0.f;
            const float wh = (j1 < NHID_) ? W_ih[j1*NIN_ + i] : 0.f;
            W.wi[i][p] = pk2(wl, wh);
        }
#pragma unroll
        for (int k = 0; k < NHID_; ++k) {
            const float wl = (j0 < NHID_) ? W_hh[j0*NHID_ + k] : 0.f;
            const float wh = (j1 < NHID_) ? W_hh[j1*NHID_ + k] : 0.f;
            W.wh[k][p] = pk2(wl, wh);
        }
    }

    u64 hd[NHID_];
#pragma unroll
    for (int k = 0; k < NHID_; ++k) hd[k] = dup2(0.f);

    const float* row = state + (size_t)b * (size_t)T * NIN_;

    if ((T & 3) == 0) {
        // Fast path: row base is 16B-aligned (T % 4 == 0 -> 12*T % 16 == 0).
        const float4* xr = reinterpret_cast<const float4*>(row);
        const int NC = T / 16;           // 16-step chunks, 12 float4 each
        float4 A[12], Bb[12];
        if (NC > 0) {
#pragma unroll
            for (int i = 0; i < 12; ++i) A[i] = xr[i];
        }
        int c = 0;
        while (c < NC) {
            if (c + 1 < NC) {
#pragma unroll
                for (int i = 0; i < 12; ++i) Bb[i] = xr[(size_t)(c + 1) * 12 + i];
            }
            steps16(A, W, hd);
            if (c + 2 < NC) {
#pragma unroll
                for (int i = 0; i < 12; ++i) A[i] = xr[(size_t)(c + 2) * 12 + i];
            }
            if (c + 1 < NC) steps16(Bb, W, hd);
            c += 2;
        }
        // Remainder steps (T % 16), scalar loads.
        for (int t = NC * 16; t < T; ++t)
            rnn_step(row[3*t + 0], row[3*t + 1], row[3*t + 2], W, hd);
    } else {
        // Generic fallback (unused for T=2048): scalar loads each step.
        for (int t = 0; t < T; ++t)
            rnn_step(row[3*t + 0], row[3*t + 1], row[3*t + 2], W, hd);
    }

    // ---- out = tanh(W_out . h_T + b_out), NOUT = 1 ----
    const float h0 = lo2(hd[0]), h1 = lo2(hd[1]), h2 = lo2(hd[2]);
    const float h3 = lo2(hd[3]), h4 = lo2(hd[4]);
    float acc = b_out[0];
    acc = fmaf(h0, W_out[0],
          fmaf(h1, W_out[1],
          fmaf(h2, W_out[2],
          fmaf(h3, W_out[3],
          fmaf(h4, W_out[4], acc)))));
    out[b] = tanhf(acc);
}

extern "C" void kernel_launch(void* const* d_in, const int* in_sizes, int n_in,
                              void* d_out, int out_size) {
    const float* state = (const float*)d_in[0];   // [B, T, 3]
    const float* W_ih  = (const float*)d_in[1];   // [5, 3]
    const float* W_hh  = (const float*)d_in[2];   // [5, 5]
    const float* b_ih  = (const float*)d_in[3];   // [5]
    const float* b_hh  = (const float*)d_in[4];   // [5]
    const float* W_out = (const float*)d_in[5];   // [1, 5]
    const float* b_out = (const float*)d_in[6];   // [1]

    const int B = out_size;                       // NOUT == 1
    const int T = in_sizes[0] / (B * NIN_);

    const int blocks = (B + 31) / 32;             // 1-warp blocks -> spread across SMs
    rnn_scan_kernel<<<blocks, 32>>>(state, W_ih, W_hh, b_ih, b_hh, W_out, b_out,
                                    (float*)d_out, B, T);
}

// round 13
// speedup vs baseline: 1.1754x; 1.1638x over previous
#include <cuda_runtime.h>

// Single-layer ReLU RNN (batch_first), h0 = 0, out = tanh(W_out h_T + b_out).
// TWO lanes per batch row (even lane: hidden units 0..2, odd lane: 3,4 + pad).
// Per step per lane: 27 scalar FFMA + 3 FMNMX + 3 SHFL.XOR — halves the
// per-thread FMA stream vs the 1-thread/row version and doubles active SMSPs
// (256 warps, one per SMSP on 128 SMs, single wave).
// Input row streamed via double-buffered LDG.128 (both lanes of a pair load
// the same addresses; L1 broadcasts within the wavefront).

#define NIN_  3
#define NHID_ 5

struct Wt {
    float Wx[NIN_][3];  // [input i][local out j]
    float A[3][3];      // own-h weights  A[k][j]
    float Bw[3][3];     // partner-h weights
    float bias[3];
    float wout[3];
};

__device__ __forceinline__ void step2(float x0, float x1, float x2,
                                      const Wt& W, float (&own)[3])
{
    // exchange previous-step h with partner lane
    float o0 = __shfl_xor_sync(0xffffffffu, own[0], 1);
    float o1 = __shfl_xor_sync(0xffffffffu, own[1], 1);
    float o2 = __shfl_xor_sync(0xffffffffu, own[2], 1);
    float a[3];
#pragma unroll
    for (int j = 0; j < 3; ++j) {
        float s = fmaf(x0, W.Wx[0][j], W.bias[j]);
        s = fmaf(x1, W.Wx[1][j], s);
        s = fmaf(x2, W.Wx[2][j], s);
        s = fmaf(own[0], W.A[0][j], s);
        s = fmaf(own[1], W.A[1][j], s);
        s = fmaf(own[2], W.A[2][j], s);
        s = fmaf(o0, W.Bw[0][j], s);
        s = fmaf(o1, W.Bw[1][j], s);
        s = fmaf(o2, W.Bw[2][j], s);
        a[j] = s;
    }
#pragma unroll
    for (int j = 0; j < 3; ++j) own[j] = fmaxf(a[j], 0.f);
}

// 16 timesteps = 48 floats = 12 float4 from the register buffer.
__device__ __forceinline__ void steps16(const float4 (&bf)[12], const Wt& W, float (&own)[3]) {
#pragma unroll
    for (int g = 0; g < 4; ++g) {
        float4 p = bf[3*g + 0];
        float4 q = bf[3*g + 1];
        float4 r = bf[3*g + 2];
        step2(p.x, p.y, p.z, W, own);
        step2(p.w, q.x, q.y, W, own);
        step2(q.z, q.w, r.x, W, own);
        step2(r.y, r.z, r.w, W, own);
    }
}

__global__ void __launch_bounds__(64, 1) rnn2_scan_kernel(
    const float* __restrict__ state,
    const float* __restrict__ W_ih, const float* __restrict__ W_hh,
    const float* __restrict__ b_ih, const float* __restrict__ b_hh,
    const float* __restrict__ W_out, const float* __restrict__ b_out,
    float* __restrict__ out, int B, int T)
{
    const int tid  = blockIdx.x * 64 + threadIdx.x;
    int row        = tid >> 1;
    const int half = tid & 1;                 // 0: units 0..2, 1: units 3,4,(5=pad)
    const bool writer = (half == 0) && (row < B);
    if (row >= B) row = B - 1;                // redundant compute, no store

    // ---- lane-local weights (zero-padded for unit index 5) ----
    Wt W;
    const int ja = 3 * half;                  // base of my local outputs / own h units
    const int jb = 3 * (1 - half);            // base of partner's h units
#pragma unroll
    for (int j = 0; j < 3; ++j) {
        const int jg = ja + j;
        const bool v = (jg < NHID_);
        W.bias[j] = v ? (b_ih[jg] + b_hh[jg]) : 0.f;
        W.wout[j] = v ? W_out[jg] : 0.f;
#pragma unroll
        for (int i = 0; i < NIN_; ++i)
            W.Wx[i][j] = v ? W_ih[jg * NIN_ + i] : 0.f;
#pragma unroll
        for (int k = 0; k < 3; ++k) {
            const int ka = ja + k;            // own h unit index
            const int kb = jb + k;            // partner h unit index
            W.A[k][j]  = (v && ka < NHID_) ? W_hh[jg * NHID_ + ka] : 0.f;
            W.Bw[k][j] = (v && kb < NHID_) ? W_hh[jg * NHID_ + kb] : 0.f;
        }
    }

    float own[3] = {0.f, 0.f, 0.f};

    const float* rowp = state + (size_t)row * (size_t)T * NIN_;

    if ((T & 3) == 0) {
        // Row base is 16B-aligned (12*T bytes per row, T%4==0).
        const float4* xr = reinterpret_cast<const float4*>(rowp);
        const int NC = T / 16;                // 16-step chunks, 12 float4 each
        float4 Ab[12], Bb[12];
        if (NC > 0) {
#pragma unroll
            for (int i = 0; i < 12; ++i) Ab[i] = xr[i];
        }
        int c = 0;
        while (c < NC) {
            if (c + 1 < NC) {
#pragma unroll
                for (int i = 0; i < 12; ++i) Bb[i] = xr[(size_t)(c + 1) * 12 + i];
            }
            steps16(Ab, W, own);
            if (c + 2 < NC) {
#pragma unroll
                for (int i = 0; i < 12; ++i) Ab[i] = xr[(size_t)(c + 2) * 12 + i];
            }
            if (c + 1 < NC) steps16(Bb, W, own);
            c += 2;
        }
        for (int t = NC * 16; t < T; ++t)
            step2(rowp[3*t + 0], rowp[3*t + 1], rowp[3*t + 2], W, own);
    } else {
        for (int t = 0; t < T; ++t)
            step2(rowp[3*t + 0], rowp[3*t + 1], rowp[3*t + 2], W, own);
    }

    // ---- out = tanh(W_out . h_T + b_out), combined across the lane pair ----
    float part = fmaf(own[0], W.wout[0],
                 fmaf(own[1], W.wout[1],
                      own[2] * W.wout[2]));
    float poth = __shfl_xor_sync(0xffffffffu, part, 1);
    if (writer)
        out[row] = tanhf(part + poth + b_out[0]);
}

extern "C" void kernel_launch(void* const* d_in, const int* in_sizes, int n_in,
                              void* d_out, int out_size) {
    const float* state = (const float*)d_in[0];   // [B, T, 3]
    const float* W_ih  = (const float*)d_in[1];   // [5, 3]
    const float* W_hh  = (const float*)d_in[2];   // [5, 5]
    const float* b_ih  = (const float*)d_in[3];   // [5]
    const float* b_hh  = (const float*)d_in[4];   // [5]
    const float* W_out = (const float*)d_in[5];   // [1, 5]
    const float* b_out = (const float*)d_in[6];   // [1]

    const int B = out_size;                       // NOUT == 1
    const int T = in_sizes[0] / (B * NIN_);

    const int threads = 2 * B;                    // 2 lanes per row
    const int blocks  = (threads + 63) / 64;      // 64-thr blocks -> 2 warps/SM, 1 wave
    rnn2_scan_kernel<<<blocks, 64>>>(state, W_ih, W_hh, b_ih, b_hh, W_out, b_out,
                                     (float*)d_out, B, T);
}